// round 16
// baseline (speedup 1.0000x reference)
#include <cuda_runtime.h>
#include <cstdint>
#include <math.h>

// YOLO post-process: decode -> per-class top-256 -> greedy NMS -> per-image top-100.
#define NB 8
#define NC 80
#define NPTS 25200
#define KTOP 256
#define MAXB 100
#define NMS_T 0.6f
#define ECAP 4096
#define FCAP 2048
#define KB0 128               // key8 threshold == key16 0x4000 == d <= ~2.0 (score >= ~0.5)
#define S_GUARD 0.5600f       // > max exact score of any filtered-out element (0.55816)

typedef unsigned long long u64;

// ---------------- scratch (static device globals; no allocation) ----------------
__device__ float4 g_boxes4[NB * NPTS];                     // [B][N] yxyx
__device__ unsigned char g_key8[(size_t)NB * NC * NPTS];   // [B][C][N] approx key byte (smaller=better)
__device__ float4 g_cand_boxes4[NB * NC * KTOP];           // [B][C][K]
__device__ float  g_kept[NB * NC * KTOP];                  // [B][C][K]

__constant__ float c_anch[3][3][2] = {
    {{12.0f/640.0f, 16.0f/640.0f}, {19.0f/640.0f, 36.0f/640.0f}, {40.0f/640.0f, 28.0f/640.0f}},
    {{36.0f/640.0f, 75.0f/640.0f}, {76.0f/640.0f, 55.0f/640.0f}, {72.0f/640.0f, 146.0f/640.0f}},
    {{142.0f/640.0f,110.0f/640.0f},{192.0f/640.0f,243.0f/640.0f},{459.0f/640.0f,401.0f/640.0f}}};

__device__ __forceinline__ float sigm(float x) { return 1.0f / (1.0f + expf(-x)); }

// Schraudolph approx of e^{-x}: monotone, one-sided OVERestimate (<= +6.07% rel).
__device__ __forceinline__ float approx_em(float x) {
    float y = fmaf(x, -12102203.0f, 1065353216.0f);
    y = fminf(fmaxf(y, 0.0f), 2130706432.0f);    // clamp to [0, 0x7F000000]
    return __int_as_float((int)y);
}

// d >= 1.0 always, so bits>>16 >= 0x3F80. key8 = exact offset, saturated at 255.
__device__ __forceinline__ unsigned key8_of(float d) {
    unsigned t = (__float_as_uint(d) >> 16) - 0x3F80u;
    return t > 255u ? 255u : t;
}

// ---------------- Stage 1: decode (exact boxes; approx key bytes, FMA-only) ----------------
__global__ __launch_bounds__(256) void decode_kernel(
    const float* __restrict__ x3, const float* __restrict__ x4, const float* __restrict__ x5)
{
    __shared__ float sIn[6800];
    __shared__ float sEo1[80];

    int blk = blockIdx.x;
    int b = blk / 315;
    int t = blk - b * 315;
    const float* src; int W, lvlOff, tloc, lvl;
    if (t < 240)      { lvl = 0; W = 80; lvlOff = 0;     tloc = t;       src = x3; }
    else if (t < 300) { lvl = 1; W = 40; lvlOff = 19200; tloc = t - 240; src = x4; }
    else              { lvl = 2; W = 20; lvlOff = 24000; tloc = t - 300; src = x5; }

    int tid = threadIdx.x;
    const float4* base4 = (const float4*)(src + (size_t)b * W * W * 255 + (size_t)tloc * 6800);
    for (int i = tid; i < 1700; i += 256) ((float4*)sIn)[i] = base4[i];
    __syncthreads();

    int nGlobBase = lvlOff + tloc * 80;
    float invW = 1.0f / (float)W;

    if (tid < 80) {
        const float* d = &sIn[tid * 85];
        int nLoc = tloc * 80 + tid;
        int a = nLoc % 3;
        int cell = nLoc / 3;
        int wq = cell % W;
        int hq = cell / W;
        float xc = (sigm(d[0]) + (float)wq) * invW;
        float yc = (sigm(d[1]) + (float)hq) * invW;
        float bw = expf(d[2]) * c_anch[lvl][a][0];
        float bh = expf(d[3]) * c_anch[lvl][a][1];
        float4 bx;
        bx.x = yc - bh * 0.5f;
        bx.y = xc - bw * 0.5f;
        bx.z = yc + bh * 0.5f;
        bx.w = xc + bw * 0.5f;
        g_boxes4[(size_t)b * NPTS + nGlobBase + tid] = bx;
        sEo1[tid] = 1.0f + approx_em(d[4]);
    }
    __syncthreads();

    if (tid < 160) {
        int q = tid % 20, cg = tid / 20;
        int a0 = q * 4;
        float e0 = sEo1[a0], e1 = sEo1[a0 + 1], e2 = sEo1[a0 + 2], e3 = sEo1[a0 + 3];
        const float* p = &sIn[a0 * 85 + 5 + cg];
        unsigned char* gp = g_key8 + ((size_t)b * NC + cg) * NPTS + nGlobBase + a0;
        #pragma unroll 2
        for (int j = 0; j < 10; j++) {
            float dv0 = fmaf(approx_em(p[0]),   e0, e0);
            float dv1 = fmaf(approx_em(p[85]),  e1, e1);
            float dv2 = fmaf(approx_em(p[170]), e2, e2);
            float dv3 = fmaf(approx_em(p[255]), e3, e3);
            unsigned packed = key8_of(dv0) | (key8_of(dv1) << 8)
                            | (key8_of(dv2) << 16) | (key8_of(dv3) << 24);
            *reinterpret_cast<unsigned*>(gp) = packed;
            p += 8;
            gp += (size_t)8 * NPTS;
        }
    }
}

// ---------------- helpers ----------------
template <int NW>
__device__ __forceinline__ int blockSum(int v, int* red, int tid) {
    v += __shfl_down_sync(0xffffffffu, v, 16);
    v += __shfl_down_sync(0xffffffffu, v, 8);
    v += __shfl_down_sync(0xffffffffu, v, 4);
    v += __shfl_down_sync(0xffffffffu, v, 2);
    v += __shfl_down_sync(0xffffffffu, v, 1);
    __syncthreads();
    if ((tid & 31) == 0) red[tid >> 5] = v;
    __syncthreads();
    int s = 0;
    #pragma unroll
    for (int w = 0; w < NW; w++) s += red[w];
    return s;
}

__device__ __forceinline__ const float* row_ptr(
    int b, int n,
    const float* __restrict__ x3, const float* __restrict__ x4, const float* __restrict__ x5)
{
    if (n < 19200)      return x3 + (size_t)b * 1632000 + (size_t)n * 85;
    else if (n < 24000) return x4 + (size_t)b * 408000  + (size_t)(n - 19200) * 85;
    else                return x5 + (size_t)b * 102000  + (size_t)(n - 24000) * 85;
}

__device__ __forceinline__ u64 exact_key(
    int b, int c, int n,
    const float* __restrict__ x3, const float* __restrict__ x4, const float* __restrict__ x5)
{
    const float* s = row_ptr(b, n, x3, x4, x5);
    float sc = sigm(s[5 + c]) * sigm(s[4]);
    return ((u64)__float_as_uint(sc) << 32) | (unsigned)(~(unsigned)n);
}

// on-the-fly approx key16 (same FMA math as decode) — cold fallback only
__device__ __forceinline__ unsigned fly_key16(
    int b, int c, int n,
    const float* __restrict__ x3, const float* __restrict__ x4, const float* __restrict__ x5)
{
    const float* s = row_ptr(b, n, x3, x4, x5);
    float eo1 = 1.0f + approx_em(s[4]);
    float d = fmaf(approx_em(s[5 + c]), eo1, eo1);
    return __float_as_uint(d) >> 16;
}

__device__ __forceinline__ u64 btn_keep(u64 a, u64 b, bool up, bool lower) {
    u64 mx = a > b ? a : b;
    u64 mn = a > b ? b : a;
    return (up == lower) ? mx : mn;
}

__device__ __forceinline__ unsigned margin16(unsigned T0) {
    unsigned Tm = __float_as_uint(__uint_as_float((T0 + 1u) << 16) * 1.15f) >> 16;
    return Tm > 0x7FFFu ? 0x7FFFu : Tm;
}

// ---------------- Stage 2 ----------------
// smem: kE u64[4096]@0 (32K) | sortBuf u64[512]@32768 (4K) | red@36864 | ints@36896
// overlays (post-sort): smask[256][8]@0 (8K), sbox float4[256]@8192 (4K)
#define TKO_SB  32768
#define TKO_RED 36864
#define TKO_INT 36896
#define TK_SMEM 36928

__global__ __launch_bounds__(256) void topk_nms_kernel(
    const float* __restrict__ x3, const float* __restrict__ x4, const float* __restrict__ x5)
{
    extern __shared__ char sm[];
    u64* kE         = (u64*)sm;
    u64* sortBuf    = (u64*)(sm + TKO_SB);
    int* red        = (int*)(sm + TKO_RED);
    int* sInts      = (int*)(sm + TKO_INT);
    unsigned* smask = (unsigned*)sm;                // overlay on kE
    float4* sbox    = (float4*)(sm + 8192);         // overlay on kE

    int bc = blockIdx.x;
    int tid = threadIdx.x;
    int lane = tid & 31;
    int b = bc / NC;
    int c = bc - b * NC;
    const uint4* r4 = (const uint4*)(g_key8 + (size_t)bc * NPTS);  // 16 keys per LDG.128

    // ---- HOT: single fused sweep — exact-rescore every hit (key8 <= KB0) into kE ----
    __syncthreads();
    if (tid == 0) sInts[0] = 0;
    __syncthreads();
    {
        unsigned KK = (unsigned)KB0 * 0x01010101u;
        for (int k = 0; k < 7; k++) {               // 7*256 = 1792 >= 1575 vectors, uniform
            int i = tid + (k << 8);
            uint4 v = make_uint4(0u, 0u, 0u, 0u);
            unsigned m0 = 0, m1 = 0, m2 = 0, m3 = 0;
            if (i < NPTS / 16) {
                v = __ldg(&r4[i]);
                m0 = __vcmpleu4(v.x, KK); m1 = __vcmpleu4(v.y, KK);
                m2 = __vcmpleu4(v.z, KK); m3 = __vcmpleu4(v.w, KK);
            }
            int h = (__popc(m0) + __popc(m1) + __popc(m2) + __popc(m3)) >> 3;
            int pre = h;
            #pragma unroll
            for (int off = 1; off < 32; off <<= 1) {
                int tt = __shfl_up_sync(0xffffffffu, pre, off);
                if (lane >= off) pre += tt;
            }
            int tot = __shfl_sync(0xffffffffu, pre, 31);
            int base = 0;
            if (lane == 31 && tot > 0) base = atomicAdd(&sInts[0], tot);
            base = __shfl_sync(0xffffffffu, base, 31);
            if (h > 0) {
                int wp = base + pre - h;
                unsigned n0 = (unsigned)i * 16u;
                unsigned wm[4] = { m0, m1, m2, m3 };
                #pragma unroll
                for (int w = 0; w < 4; w++) {
                    unsigned mm = wm[w];
                    while (mm) {
                        int bit = __ffs(mm) - 1;
                        int by = bit >> 3;
                        mm &= ~(0xFFu << (by << 3));
                        int n = (int)(n0 + (unsigned)(w * 4 + by));
                        if (wp < ECAP) kE[wp] = exact_key(b, c, n, x3, x4, x5);
                        wp++;
                    }
                }
            }
        }
    }
    __syncthreads();
    int ns = sInts[0];
    bool used_hot = (ns >= KTOP && ns <= ECAP);

    // ---- COLD fallback: margin-based superset with exact keys (proven path) ----
    auto coldFill = [&]() -> int {
        auto count_fly = [&](unsigned m) -> int {
            int cl = 0;
            for (int i = tid; i < NPTS; i += 256)
                cl += (fly_key16(b, c, i, x3, x4, x5) <= m);
            return blockSum<8>(cl, red, tid);
        };
        auto collect_fly = [&](unsigned Kthr) -> int {
            __syncthreads();
            if (tid == 0) sInts[0] = 0;
            __syncthreads();
            for (int i = tid; i < NPTS; i += 256) {
                unsigned k16 = fly_key16(b, c, i, x3, x4, x5);
                if (k16 <= Kthr) {
                    int p = atomicAdd(&sInts[0], 1);
                    if (p < ECAP) kE[p] = exact_key(b, c, i, x3, x4, x5);
                }
            }
            __syncthreads();
            return sInts[0];
        };
        unsigned flo = 0x3F7Fu, fhi = 0x7FFFu;
        while (fhi - flo > 1u) {
            unsigned m = (flo + fhi) >> 1;
            int cl = count_fly(m);
            if (cl >= KTOP) fhi = m; else flo = m;
        }
        int cr = collect_fly(margin16(fhi));
        if (cr > ECAP) cr = collect_fly(fhi);     // strict retry (small set)
        return min(cr, ECAP);
    };
    if (!used_hot) ns = coldFill();

    // ---- trim to <=512 (exact 32-bit score bits) + stage + register sort 512 ----
    u64 e0 = 0, e1 = 0;
    auto stage = [&](int nsv) {
        if (nsv <= 512) {
            for (int i = tid; i < 512; i += 256) sortBuf[i] = (i < nsv) ? kE[i] : 0ULL;
            __syncthreads();
        } else {
            unsigned tlo = 0, thi = 0x3F800000u;
            bool done = false;
            while (!done && (thi - tlo) > 1u) {
                unsigned m = (tlo + thi) >> 1;
                int cl = 0;
                for (int i = tid; i < nsv; i += 256) cl += ((unsigned)(kE[i] >> 32) >= m);
                cl = blockSum<8>(cl, red, tid);
                if (cl >= KTOP) { tlo = m; done = (cl <= 512); }
                else thi = m;
            }
            __syncthreads();
            if (tid == 0) sInts[0] = 0;
            __syncthreads();
            int iters = (nsv + 255) >> 8;
            for (int k = 0; k < iters; k++) {
                int i = tid + (k << 8);
                bool has = false; u64 kk = 0;
                if (i < nsv) { kk = kE[i]; has = ((unsigned)(kk >> 32) >= tlo); }
                unsigned ball = __ballot_sync(0xffffffffu, has);
                int nh = __popc(ball);
                int base = 0;
                if (lane == 0 && nh > 0) base = atomicAdd(&sInts[0], nh);
                base = __shfl_sync(0xffffffffu, base, 0);
                int rk = __popc(ball & ((1u << lane) - 1u));
                if (has && base + rk < 512) sortBuf[base + rk] = kk;
            }
            __syncthreads();
            int c2 = min(sInts[0], 512);
            for (int i = c2 + tid; i < 512; i += 256) sortBuf[i] = 0ULL;
            __syncthreads();
        }
    };
    auto do_sort = [&]() {
        e0 = sortBuf[tid];
        e1 = sortBuf[tid + 256];
        __syncthreads();
        #pragma unroll
        for (unsigned k = 2; k <= 512; k <<= 1) {
            #pragma unroll
            for (unsigned j = k >> 1; j > 0; j >>= 1) {
                bool up0 = ((tid & k) == 0);
                bool up1 = (((tid + 256) & k) == 0);
                if (j == 256) {
                    u64 a = e0, bb = e1;
                    e0 = btn_keep(a, bb, up0, true);
                    e1 = btn_keep(bb, a, up1, false);
                } else if (j >= 32) {
                    sortBuf[tid] = e0; sortBuf[tid + 256] = e1;
                    __syncthreads();
                    u64 p0 = sortBuf[tid ^ j];
                    u64 p1 = sortBuf[(tid + 256) ^ j];
                    bool lower = ((tid & j) == 0);
                    e0 = btn_keep(e0, p0, up0, lower);
                    e1 = btn_keep(e1, p1, up1, lower);
                    __syncthreads();
                } else {
                    u64 p0 = __shfl_xor_sync(0xffffffffu, e0, j);
                    u64 p1 = __shfl_xor_sync(0xffffffffu, e1, j);
                    bool lower = ((tid & j) == 0);
                    e0 = btn_keep(e0, p0, up0, lower);
                    e1 = btn_keep(e1, p1, up1, lower);
                }
            }
        }
    };

    stage(ns);
    do_sort();

    if (used_hot) {
        // exactness guard: if rank-255 exact score <= S_GUARD, a filtered-out element
        // (exact score <= 0.55816) could belong to the true top-256 -> cold retry.
        if (tid == 255) sInts[3] = (int)(unsigned)(e0 >> 32);
        __syncthreads();
        float s255 = __uint_as_float((unsigned)sInts[3]);
        __syncthreads();
        if (!(s255 > S_GUARD)) {
            ns = coldFill();
            stage(ns);
            do_sort();
        }
    }
    // rank-tid element == e0 (>=256 genuine candidates guaranteed)

    // ---- NMS on the exact sorted top-256 ----
    float val = __uint_as_float((unsigned)(e0 >> 32));
    unsigned n = ~(unsigned)e0;
    float4 bb4 = g_boxes4[(size_t)b * NPTS + n];
    g_cand_boxes4[(size_t)bc * KTOP + tid] = bb4;
    __syncthreads();          // kE region dead; overlays become valid
    sbox[tid] = bb4;
    float ar = (bb4.z - bb4.x) * (bb4.w - bb4.y);
    __syncthreads();

    unsigned m8[8];
    #pragma unroll
    for (int w = 0; w < 8; w++) m8[w] = 0;
    float y0 = bb4.x, x0 = bb4.y, y1 = bb4.z, x1 = bb4.w;
    int jstart = tid & ~31;
    for (int j = jstart; j < KTOP; ++j) {
        float4 bj = sbox[j];
        if (j > tid) {
            float iy = fmaxf(fminf(y1, bj.z) - fmaxf(y0, bj.x), 0.0f);
            float ix = fmaxf(fminf(x1, bj.w) - fmaxf(x0, bj.y), 0.0f);
            float inter = iy * ix;
            float arj = (bj.z - bj.x) * (bj.w - bj.y);
            float uni = ar + arj - inter;
            if (inter > NMS_T * fmaxf(uni, 1e-9f)) m8[j >> 5] |= (1u << (j & 31));
        }
    }
    #pragma unroll
    for (int w = 0; w < 8; w++) smask[tid * 8 + w] = m8[w];
    __syncthreads();

    if (tid < 32) {
        unsigned kp = 0xFFFFFFFFu;
        for (int i = 0; i < KTOP; ++i) {
            unsigned kw = __shfl_sync(0xffffffffu, kp, i >> 5);
            bool alive = (kw >> (i & 31)) & 1u;
            if (alive && tid < 8) kp &= ~smask[i * 8 + tid];
        }
        if (tid < 8) red[tid] = (int)kp;
    }
    __syncthreads();

    bool keep = ((unsigned)red[tid >> 5] >> (tid & 31)) & 1u;
    g_kept[(size_t)bc * KTOP + tid] = keep ? val : 0.0f;
}

// ---------------- Stage 3: per-image top-100 (2-level histogram + exact sort) ----------------
#define F_VAL  0
#define F_KEYS 81920
#define F_RED  98304
#define F_INTS 98432
#define F_SMEM 98464

__global__ __launch_bounds__(1024) void final_kernel(float* __restrict__ out)
{
    extern __shared__ char fsm[];
    uint4* v4  = (uint4*)(fsm + F_VAL);
    u64* fkeys = (u64*)(fsm + F_KEYS);
    unsigned* fh = (unsigned*)(fsm + F_KEYS);    // histogram overlay (consumed before fkeys)
    int* red   = (int*)(fsm + F_RED);
    int* ints  = (int*)(fsm + F_INTS);

    int b = blockIdx.x, tid = threadIdx.x;
    const uint4* row4 = (const uint4*)(g_kept + (size_t)b * NC * KTOP);

    int cpos = 0;
    for (int i = tid; i < NC * KTOP / 4; i += 1024) {
        uint4 v = row4[i];
        v4[i] = v;
        cpos += (v.x >= 1u) + (v.y >= 1u) + (v.z >= 1u) + (v.w >= 1u);
    }
    __syncthreads();
    cpos = blockSum<32>(cpos, red, tid);

    int t16 = 0;
    if (cpos >= MAXB) {
        for (int i = tid; i < 512; i += 1024) fh[i] = 0;
        __syncthreads();
        unsigned hb = ((unsigned)(tid >> 5) & 7u) * 64u;
        for (int i = tid; i < NC * KTOP / 4; i += 1024) {
            uint4 v = v4[i];
            if (v.x >= 1u) atomicAdd(&fh[hb + (v.x >> 24)], 1u);
            if (v.y >= 1u) atomicAdd(&fh[hb + (v.y >> 24)], 1u);
            if (v.z >= 1u) atomicAdd(&fh[hb + (v.z >> 24)], 1u);
            if (v.w >= 1u) atomicAdd(&fh[hb + (v.w >> 24)], 1u);
        }
        __syncthreads();
        if (tid < 64) {
            unsigned s = 0;
            #pragma unroll
            for (int w = 0; w < 8; w++) s += fh[w * 64 + tid];
            fh[tid] = s;
        }
        __syncthreads();
        if (tid == 0) {
            int cum = 0, cb = 0, above = 0;
            for (int q = 63; q >= 0; q--) {
                int nc2 = cum + (int)fh[q];
                if (nc2 >= MAXB) { cb = q; above = cum; break; }
                cum = nc2;
            }
            ints[2] = cb; ints[3] = above;
        }
        __syncthreads();
        unsigned CB = (unsigned)ints[2];
        int above = ints[3];
        for (int i = tid; i < 2048; i += 1024) fh[i] = 0;
        __syncthreads();
        unsigned hb2 = ((unsigned)(tid >> 5) & 7u) * 256u;
        for (int i = tid; i < NC * KTOP / 4; i += 1024) {
            uint4 v = v4[i];
            if (v.x >= 1u && (v.x >> 24) == CB) atomicAdd(&fh[hb2 + ((v.x >> 16) & 0xFFu)], 1u);
            if (v.y >= 1u && (v.y >> 24) == CB) atomicAdd(&fh[hb2 + ((v.y >> 16) & 0xFFu)], 1u);
            if (v.z >= 1u && (v.z >> 24) == CB) atomicAdd(&fh[hb2 + ((v.z >> 16) & 0xFFu)], 1u);
            if (v.w >= 1u && (v.w >> 24) == CB) atomicAdd(&fh[hb2 + ((v.w >> 16) & 0xFFu)], 1u);
        }
        __syncthreads();
        if (tid < 256) {
            unsigned s = 0;
            #pragma unroll
            for (int w = 0; w < 8; w++) s += fh[w * 256 + tid];
            fh[tid] = s;
        }
        __syncthreads();
        if (tid == 0) {
            int cum = above, fb = 0;
            for (int q = 255; q >= 0; q--) { cum += (int)fh[q]; if (cum >= MAXB) { fb = q; break; } }
            ints[2] = (int)((CB << 8) | (unsigned)fb);
        }
        __syncthreads();
        t16 = ints[2];
    }
    unsigned Tb = (unsigned)t16 << 16;
    if (Tb < 1u) Tb = 1u;               // exclude suppressed zeros

    __syncthreads();
    if (tid == 0) { ints[0] = 0; ints[1] = 0; }
    __syncthreads();
    for (int i = tid; i < NC * KTOP / 4; i += 1024) {
        uint4 v = v4[i]; int n0 = i * 4; int p;
        if (v.x >= Tb) { p = atomicAdd(&ints[0], 1); if (p < FCAP) fkeys[p] = ((u64)v.x << 32) | (unsigned)(~(unsigned)n0); }
        if (v.y >= Tb) { p = atomicAdd(&ints[0], 1); if (p < FCAP) fkeys[p] = ((u64)v.y << 32) | (unsigned)(~(unsigned)(n0+1)); }
        if (v.z >= Tb) { p = atomicAdd(&ints[0], 1); if (p < FCAP) fkeys[p] = ((u64)v.z << 32) | (unsigned)(~(unsigned)(n0+2)); }
        if (v.w >= Tb) { p = atomicAdd(&ints[0], 1); if (p < FCAP) fkeys[p] = ((u64)v.w << 32) | (unsigned)(~(unsigned)(n0+3)); }
    }
    __syncthreads();
    int cnt = min(ints[0], FCAP);
    int S = 128; while (S < cnt) S <<= 1;
    for (int i = cnt + tid; i < S; i += 1024) fkeys[i] = 0ULL;
    __syncthreads();

    for (unsigned k = 2; k <= (unsigned)S; k <<= 1) {
        for (unsigned j = k >> 1; j > 0; j >>= 1) {
            for (unsigned i = tid; i < (unsigned)S; i += 1024) {
                unsigned l = i ^ j;
                if (l > i) {
                    u64 a = fkeys[i], bb = fkeys[l];
                    bool up = ((i & k) == 0);
                    if (up ? (a < bb) : (a > bb)) { fkeys[i] = bb; fkeys[l] = a; }
                }
            }
            __syncthreads();
        }
    }

    if (tid < MAXB) {
        u64 wk = fkeys[tid];
        float val = __uint_as_float((unsigned)(wk >> 32));
        bool valid = (wk != 0ULL) && (val > 0.0f);
        float4 bx = make_float4(0.f, 0.f, 0.f, 0.f);
        float cls = 0.0f, sc = 0.0f;
        if (valid) {
            unsigned flat = ~(unsigned)wk;
            int c = (int)(flat >> 8);
            int k2 = (int)(flat & 255);
            float4 bb = g_cand_boxes4[((size_t)b * NC + c) * KTOP + k2];
            bx.x = fminf(fmaxf(bb.x, 0.0f), 1.0f);
            bx.y = fminf(fmaxf(bb.y, 0.0f), 1.0f);
            bx.z = fminf(fmaxf(bb.z, 0.0f), 1.0f);
            bx.w = fminf(fmaxf(bb.w, 0.0f), 1.0f);
            cls = (float)c;
            sc = val;
            atomicAdd(&ints[1], 1);
        }
        ((float4*)out)[b * MAXB + tid] = bx;                 // nb
        out[NB * 400 + b * MAXB + tid] = cls;                // nc
        out[NB * 500 + b * MAXB + tid] = sc;                 // ns
    }
    __syncthreads();
    if (tid == 0) out[NB * 600 + b] = (float)ints[1];        // num_detections
}

// ---------------- launch ----------------
extern "C" void kernel_launch(void* const* d_in, const int* in_sizes, int n_in,
                              void* d_out, int out_size)
{
    const float* x3 = (const float*)d_in[0];
    const float* x4 = (const float*)d_in[1];
    const float* x5 = (const float*)d_in[2];
    float* out = (float*)d_out;

    cudaFuncSetAttribute(topk_nms_kernel, cudaFuncAttributeMaxDynamicSharedMemorySize, TK_SMEM);
    cudaFuncSetAttribute(final_kernel, cudaFuncAttributeMaxDynamicSharedMemorySize, F_SMEM);

    decode_kernel<<<NB * 315, 256>>>(x3, x4, x5);
    topk_nms_kernel<<<NB * NC, 256, TK_SMEM>>>(x3, x4, x5);
    final_kernel<<<NB, 1024, F_SMEM>>>(out);
}